// round 12
// baseline (speedup 1.0000x reference)
#include <cuda_runtime.h>
#include <cuda_fp16.h>
#include <math.h>

#define NN 80000
#define DD 64
#define EE 1280000
#define CAP 128   // padded adjacency capacity per node (Poisson(16) tail ~0 at 64)

// Scratch (__device__ globals; no allocation allowed in kernel_launch)
__device__ uint2 g_hH[NN * 16];    // h = X@W packed fp16 (row = 32 uints = 64 halves)
__device__ uint2 g_H2[NN * 16];    // H = relu(...) packed fp16
__device__ float g_gg[NN];
__device__ int   g_cnt[NN];        // out-degree (gate denominator)
__device__ int   g_deg[NN];        // in-degree == build cursor
__device__ int   g_adj[NN * CAP];  // padded adjacency: srcs bucketed by dst

// ---------------------------------------------------------------------------
__global__ void k_init(int n) {
    int i = blockIdx.x * blockDim.x + threadIdx.x;
    if (i < n) {
        g_deg[i] = 0;
        g_cnt[i] = 0;
        g_gg[i]  = 0.f;
    }
}

// ---------------------------------------------------------------------------
// k_build: ONE indexing pass. The slot-claim atomic IS the degree counter;
// no prefix scan, no separate k_deg. cnt[src] counted alongside (no return
// value needed -> REDG-aggregatable).
// ---------------------------------------------------------------------------
__global__ void k_build(const int* __restrict__ src, const int* __restrict__ dst, int e) {
    int i = blockIdx.x * blockDim.x + threadIdx.x;
    if (i < e) {
        int s = src[i], d = dst[i];
        int pos = atomicAdd(&g_deg[d], 1);
        if (pos < CAP) g_adj[d * CAP + pos] = s;
        atomicAdd(&g_cnt[s], 1);
    }
}

// ---------------------------------------------------------------------------
// k_gemm: h = X @ W, 4x4 register tile (measured 27us). fp16 packed output.
// ---------------------------------------------------------------------------
#define XS_STRIDE 68
__global__ void __launch_bounds__(256) k_gemm(const float* __restrict__ X,
                                              const float* __restrict__ W, int n) {
    __shared__ float  Xsh[64 * XS_STRIDE];   // Xsh[k][row]
    __shared__ float4 Wsh[64 * 16];          // Wsh[k][cg]

    int tid  = threadIdx.x;
    int base = blockIdx.x * 64;

    const float4* W4 = (const float4*)W;
#pragma unroll
    for (int i = 0; i < 4; i++) Wsh[tid + 256 * i] = W4[tid + 256 * i];

#pragma unroll
    for (int i = 0; i < 4; i++) {
        int idx = tid + 256 * i;
        int row = idx & 63;
        int kk  = idx >> 6;
        int gr  = base + row;
        float4 v = (gr < n) ? ((const float4*)(X + (size_t)gr * 64))[kk]
                            : make_float4(0.f, 0.f, 0.f, 0.f);
        int k0 = kk * 4;
        Xsh[(k0 + 0) * XS_STRIDE + row] = v.x;
        Xsh[(k0 + 1) * XS_STRIDE + row] = v.y;
        Xsh[(k0 + 2) * XS_STRIDE + row] = v.z;
        Xsh[(k0 + 3) * XS_STRIDE + row] = v.w;
    }
    __syncthreads();

    int cg = tid & 15;
    int rg = tid >> 4;

    float4 acc0 = make_float4(0.f, 0.f, 0.f, 0.f);
    float4 acc1 = make_float4(0.f, 0.f, 0.f, 0.f);
    float4 acc2 = make_float4(0.f, 0.f, 0.f, 0.f);
    float4 acc3 = make_float4(0.f, 0.f, 0.f, 0.f);

#pragma unroll
    for (int k = 0; k < 64; k++) {
        float4 w  = Wsh[k * 16 + cg];
        float4 xv = *(const float4*)&Xsh[k * XS_STRIDE + rg * 4];
        acc0.x += xv.x * w.x; acc0.y += xv.x * w.y; acc0.z += xv.x * w.z; acc0.w += xv.x * w.w;
        acc1.x += xv.y * w.x; acc1.y += xv.y * w.y; acc1.z += xv.y * w.z; acc1.w += xv.y * w.w;
        acc2.x += xv.z * w.x; acc2.y += xv.z * w.y; acc2.z += xv.z * w.z; acc2.w += xv.z * w.w;
        acc3.x += xv.w * w.x; acc3.y += xv.w * w.y; acc3.z += xv.w * w.z; acc3.w += xv.w * w.w;
    }

    int r0 = base + rg * 4;
#pragma unroll
    for (int j = 0; j < 4; j++) {
        float4 a = (j == 0) ? acc0 : (j == 1) ? acc1 : (j == 2) ? acc2 : acc3;
        int row = r0 + j;
        if (row < n) {
            __half2 lo = __floats2half2_rn(a.x, a.y);
            __half2 hi = __floats2half2_rn(a.z, a.w);
            uint2 p;
            p.x = *(unsigned int*)&lo;
            p.y = *(unsigned int*)&hi;
            g_hH[row * 16 + cg] = p;
        }
    }
}

// ---------------------------------------------------------------------------
// k_agg: warp per node (padded adjacency), 4-way unrolled. dinv computed
// inline (rsqrtf of degree -- int load replaces the former float dinv load).
// Fuses self-loop, bias, relu, fp16 pack. Lane l owns feature cols 2l, 2l+1.
// ---------------------------------------------------------------------------
__global__ void __launch_bounds__(256) k_agg(const float* __restrict__ b, int n) {
    int warp = (blockIdx.x * blockDim.x + threadIdx.x) >> 5;
    int lane = threadIdx.x & 31;
    if (warp >= n) return;
    int d = warp;

    const unsigned int* h2 = (const unsigned int*)g_hH;
    int cnt = g_deg[d];
    float dinv_d = rsqrtf((float)(cnt + 1));   // +1 self loop
    const int* row = &g_adj[d * CAP];

    float2 acc = make_float2(0.f, 0.f);

    int j = 0;
    for (; j + 4 <= cnt; j += 4) {
        int sa = row[j + 0];
        int sb = row[j + 1];
        int sc = row[j + 2];
        int sd = row[j + 3];
        float na = rsqrtf((float)(g_deg[sa] + 1)) * dinv_d;
        float nb = rsqrtf((float)(g_deg[sb] + 1)) * dinv_d;
        float nc = rsqrtf((float)(g_deg[sc] + 1)) * dinv_d;
        float nd = rsqrtf((float)(g_deg[sd] + 1)) * dinv_d;
        float2 ha = __half22float2(*(const __half2*)&h2[sa * 32 + lane]);
        float2 hb = __half22float2(*(const __half2*)&h2[sb * 32 + lane]);
        float2 hc = __half22float2(*(const __half2*)&h2[sc * 32 + lane]);
        float2 hd = __half22float2(*(const __half2*)&h2[sd * 32 + lane]);
        acc.x = fmaf(ha.x, na, acc.x); acc.y = fmaf(ha.y, na, acc.y);
        acc.x = fmaf(hb.x, nb, acc.x); acc.y = fmaf(hb.y, nb, acc.y);
        acc.x = fmaf(hc.x, nc, acc.x); acc.y = fmaf(hc.y, nc, acc.y);
        acc.x = fmaf(hd.x, nd, acc.x); acc.y = fmaf(hd.y, nd, acc.y);
    }
    for (; j < cnt; j++) {
        int s = row[j];
        float norm = rsqrtf((float)(g_deg[s] + 1)) * dinv_d;
        float2 hv = __half22float2(*(const __half2*)&h2[s * 32 + lane]);
        acc.x = fmaf(hv.x, norm, acc.x);
        acc.y = fmaf(hv.y, norm, acc.y);
    }

    float sl = dinv_d * dinv_d;
    float2 hd0 = __half22float2(*(const __half2*)&h2[d * 32 + lane]);
    float2 bb  = ((const float2*)b)[lane];
    float rx = fmaxf(fmaf(hd0.x, sl, acc.x) + bb.x, 0.f);
    float ry = fmaxf(fmaf(hd0.y, sl, acc.y) + bb.y, 0.f);
    __half2 hh = __floats2half2_rn(rx, ry);
    ((unsigned int*)g_H2)[d * 32 + lane] = *(unsigned int*)&hh;
}

// ---------------------------------------------------------------------------
// k_gate: edge-parallel (measured-good form). gg[src] += ||H_s - H_d||^2.
// 8 lanes/edge, each lane one uint4 (16B); scalar atomic per edge.
// ---------------------------------------------------------------------------
__global__ void k_gate(const int* __restrict__ src, const int* __restrict__ dst, int e) {
    int t = blockIdx.x * blockDim.x + threadIdx.x;
    int ei = t >> 3;
    int lane = t & 7;
    if (ei >= e) return;
    int r = src[ei];
    int c = dst[ei];
    const uint4* H = (const uint4*)g_H2;
    uint4 a = __ldg(&H[r * 8 + lane]);
    uint4 b = __ldg(&H[c * 8 + lane]);
    const unsigned int* au = (const unsigned int*)&a;
    const unsigned int* bu = (const unsigned int*)&b;
    float s = 0.f;
#pragma unroll
    for (int j = 0; j < 4; j++) {
        float2 fa = __half22float2(*(const __half2*)&au[j]);
        float2 fb = __half22float2(*(const __half2*)&bu[j]);
        float d0 = fa.x - fb.x;
        float d1 = fa.y - fb.y;
        s = fmaf(d0, d0, s);
        s = fmaf(d1, d1, s);
    }
    s += __shfl_xor_sync(0xffffffffu, s, 4);
    s += __shfl_xor_sync(0xffffffffu, s, 2);
    s += __shfl_xor_sync(0xffffffffu, s, 1);
    if (lane == 0) atomicAdd(&g_gg[r], s);
}

__global__ void k_out(float* __restrict__ out, int n) {
    int i = blockIdx.x * blockDim.x + threadIdx.x;
    if (i < n) out[i] = tanhf(g_gg[i] / fmaxf((float)g_cnt[i], 1.f));
}

// ---------------------------------------------------------------------------
extern "C" void kernel_launch(void* const* d_in, const int* in_sizes, int n_in,
                              void* d_out, int out_size) {
    const float* X  = (const float*)d_in[0];
    const int*   ei = (const int*)d_in[1];
    const float* W  = (const float*)d_in[2];
    const float* b  = (const float*)d_in[3];
    float* out = (float*)d_out;

    int n = in_sizes[0] / DD;   // 80000
    int e = in_sizes[1] / 2;    // 1280000
    const int* src = ei;
    const int* dst = ei + e;

    const int T = 256;
    int g_n    = (n + T - 1) / T;
    int g_e    = (e + T - 1) / T;
    int g_rows = (n + 63) / 64;
    int g_warp = (n * 32 + T - 1) / T;
    long long e8 = (long long)e * 8;
    int g_e8 = (int)((e8 + T - 1) / T);

    k_init <<<g_n, T>>>(n);
    k_build<<<g_e, T>>>(src, dst, e);
    k_gemm <<<g_rows, T>>>(X, W, n);
    k_agg  <<<g_warp, T>>>(b, n);
    k_gate <<<g_e8, T>>>(src, dst, e);
    k_out  <<<g_n, T>>>(out, n);
}

// round 13
// speedup vs baseline: 1.1061x; 1.1061x over previous
#include <cuda_runtime.h>
#include <cuda_fp16.h>
#include <math.h>

#define NN 80000
#define DD 64
#define EE 1280000
#define CAP 128   // padded adjacency capacity per node (Poisson(16) tail ~0 at 64)

// Scratch (__device__ globals; no allocation allowed in kernel_launch)
__device__ uint2 g_hH[NN * 16];    // h' = (X@W)*dinv packed fp16 (32 uints/row)
__device__ uint2 g_H2[NN * 16];    // H = relu(...) packed fp16
__device__ float g_gg[NN];
__device__ int   g_cnt[NN];        // out-degree (gate denominator)
__device__ int   g_deg[NN];        // in-degree == build cursor
__device__ int   g_adj[NN * CAP];  // padded adjacency: srcs bucketed by dst

// ---------------------------------------------------------------------------
__global__ void k_init(int n) {
    int i = blockIdx.x * blockDim.x + threadIdx.x;
    if (i < n) {
        g_deg[i] = 0;
        g_cnt[i] = 0;
        g_gg[i]  = 0.f;
    }
}

// ---------------------------------------------------------------------------
// k_build: ONE indexing pass. Slot-claim atomic IS the degree counter.
// ---------------------------------------------------------------------------
__global__ void k_build(const int* __restrict__ src, const int* __restrict__ dst, int e) {
    int i = blockIdx.x * blockDim.x + threadIdx.x;
    if (i < e) {
        int s = src[i], d = dst[i];
        int pos = atomicAdd(&g_deg[d], 1);
        if (pos < CAP) g_adj[d * CAP + pos] = s;
        atomicAdd(&g_cnt[s], 1);
    }
}

// ---------------------------------------------------------------------------
// k_gemm: h' = (X @ W) * dinv_row, 4x4 register tile. dinv folded into the
// pack epilogue (runs after k_build, so g_deg is final). fp16 packed output.
// ---------------------------------------------------------------------------
#define XS_STRIDE 68
__global__ void __launch_bounds__(256) k_gemm(const float* __restrict__ X,
                                              const float* __restrict__ W, int n) {
    __shared__ float  Xsh[64 * XS_STRIDE];   // Xsh[k][row]
    __shared__ float4 Wsh[64 * 16];          // Wsh[k][cg]

    int tid  = threadIdx.x;
    int base = blockIdx.x * 64;

    const float4* W4 = (const float4*)W;
#pragma unroll
    for (int i = 0; i < 4; i++) Wsh[tid + 256 * i] = W4[tid + 256 * i];

#pragma unroll
    for (int i = 0; i < 4; i++) {
        int idx = tid + 256 * i;
        int row = idx & 63;
        int kk  = idx >> 6;
        int gr  = base + row;
        float4 v = (gr < n) ? ((const float4*)(X + (size_t)gr * 64))[kk]
                            : make_float4(0.f, 0.f, 0.f, 0.f);
        int k0 = kk * 4;
        Xsh[(k0 + 0) * XS_STRIDE + row] = v.x;
        Xsh[(k0 + 1) * XS_STRIDE + row] = v.y;
        Xsh[(k0 + 2) * XS_STRIDE + row] = v.z;
        Xsh[(k0 + 3) * XS_STRIDE + row] = v.w;
    }
    __syncthreads();

    int cg = tid & 15;
    int rg = tid >> 4;

    float4 acc0 = make_float4(0.f, 0.f, 0.f, 0.f);
    float4 acc1 = make_float4(0.f, 0.f, 0.f, 0.f);
    float4 acc2 = make_float4(0.f, 0.f, 0.f, 0.f);
    float4 acc3 = make_float4(0.f, 0.f, 0.f, 0.f);

#pragma unroll
    for (int k = 0; k < 64; k++) {
        float4 w  = Wsh[k * 16 + cg];
        float4 xv = *(const float4*)&Xsh[k * XS_STRIDE + rg * 4];
        acc0.x += xv.x * w.x; acc0.y += xv.x * w.y; acc0.z += xv.x * w.z; acc0.w += xv.x * w.w;
        acc1.x += xv.y * w.x; acc1.y += xv.y * w.y; acc1.z += xv.y * w.z; acc1.w += xv.y * w.w;
        acc2.x += xv.z * w.x; acc2.y += xv.z * w.y; acc2.z += xv.z * w.z; acc2.w += xv.z * w.w;
        acc3.x += xv.w * w.x; acc3.y += xv.w * w.y; acc3.z += xv.w * w.z; acc3.w += xv.w * w.w;
    }

    int r0 = base + rg * 4;
#pragma unroll
    for (int j = 0; j < 4; j++) {
        float4 a = (j == 0) ? acc0 : (j == 1) ? acc1 : (j == 2) ? acc2 : acc3;
        int row = r0 + j;
        if (row < n) {
            float di = rsqrtf((float)(g_deg[row] + 1));   // fold dinv into h'
            __half2 lo = __floats2half2_rn(a.x * di, a.y * di);
            __half2 hi = __floats2half2_rn(a.z * di, a.w * di);
            uint2 p;
            p.x = *(unsigned int*)&lo;
            p.y = *(unsigned int*)&hi;
            g_hH[row * 16 + cg] = p;
        }
    }
}

// ---------------------------------------------------------------------------
// k_agg: warp per node. agg = dinv_d * (sum_s h'[s] + h'[d]).
// Inner loop per neighbor: idx load + h' load + convert + 2 FADD. No deg
// load, no rsqrt, no fmul. 4-way unrolled for MLP. Fuses bias/relu/pack.
// ---------------------------------------------------------------------------
__global__ void __launch_bounds__(256) k_agg(const float* __restrict__ b, int n) {
    int warp = (blockIdx.x * blockDim.x + threadIdx.x) >> 5;
    int lane = threadIdx.x & 31;
    if (warp >= n) return;
    int d = warp;

    const unsigned int* h2 = (const unsigned int*)g_hH;
    int cnt = g_deg[d];
    float dinv_d = rsqrtf((float)(cnt + 1));   // +1 self loop
    const int* row = &g_adj[d * CAP];

    float2 acc = make_float2(0.f, 0.f);

    int j = 0;
    for (; j + 4 <= cnt; j += 4) {
        int sa = row[j + 0];
        int sb = row[j + 1];
        int sc = row[j + 2];
        int sd = row[j + 3];
        float2 ha = __half22float2(*(const __half2*)&h2[sa * 32 + lane]);
        float2 hb = __half22float2(*(const __half2*)&h2[sb * 32 + lane]);
        float2 hc = __half22float2(*(const __half2*)&h2[sc * 32 + lane]);
        float2 hd = __half22float2(*(const __half2*)&h2[sd * 32 + lane]);
        acc.x += ha.x + hb.x + hc.x + hd.x;
        acc.y += ha.y + hb.y + hc.y + hd.y;
    }
    for (; j < cnt; j++) {
        int s = row[j];
        float2 hv = __half22float2(*(const __half2*)&h2[s * 32 + lane]);
        acc.x += hv.x;
        acc.y += hv.y;
    }

    // self loop contributes h'[d] (one more dinv_d applied below with the rest)
    float2 hd0 = __half22float2(*(const __half2*)&h2[d * 32 + lane]);
    acc.x += hd0.x;
    acc.y += hd0.y;

    float2 bb = ((const float2*)b)[lane];
    float rx = fmaxf(fmaf(acc.x, dinv_d, bb.x), 0.f);
    float ry = fmaxf(fmaf(acc.y, dinv_d, bb.y), 0.f);
    __half2 hh = __floats2half2_rn(rx, ry);
    ((unsigned int*)g_H2)[d * 32 + lane] = *(unsigned int*)&hh;
}

// ---------------------------------------------------------------------------
// k_gate: edge-parallel (measured-good form). gg[src] += ||H_s - H_d||^2.
// 8 lanes/edge, each lane one uint4 (16B); scalar atomic per edge.
// ---------------------------------------------------------------------------
__global__ void k_gate(const int* __restrict__ src, const int* __restrict__ dst, int e) {
    int t = blockIdx.x * blockDim.x + threadIdx.x;
    int ei = t >> 3;
    int lane = t & 7;
    if (ei >= e) return;
    int r = src[ei];
    int c = dst[ei];
    const uint4* H = (const uint4*)g_H2;
    uint4 a = __ldg(&H[r * 8 + lane]);
    uint4 b = __ldg(&H[c * 8 + lane]);
    const unsigned int* au = (const unsigned int*)&a;
    const unsigned int* bu = (const unsigned int*)&b;
    float s = 0.f;
#pragma unroll
    for (int j = 0; j < 4; j++) {
        float2 fa = __half22float2(*(const __half2*)&au[j]);
        float2 fb = __half22float2(*(const __half2*)&bu[j]);
        float d0 = fa.x - fb.x;
        float d1 = fa.y - fb.y;
        s = fmaf(d0, d0, s);
        s = fmaf(d1, d1, s);
    }
    s += __shfl_xor_sync(0xffffffffu, s, 4);
    s += __shfl_xor_sync(0xffffffffu, s, 2);
    s += __shfl_xor_sync(0xffffffffu, s, 1);
    if (lane == 0) atomicAdd(&g_gg[r], s);
}

__global__ void k_out(float* __restrict__ out, int n) {
    int i = blockIdx.x * blockDim.x + threadIdx.x;
    if (i < n) out[i] = tanhf(g_gg[i] / fmaxf((float)g_cnt[i], 1.f));
}

// ---------------------------------------------------------------------------
extern "C" void kernel_launch(void* const* d_in, const int* in_sizes, int n_in,
                              void* d_out, int out_size) {
    const float* X  = (const float*)d_in[0];
    const int*   ei = (const int*)d_in[1];
    const float* W  = (const float*)d_in[2];
    const float* b  = (const float*)d_in[3];
    float* out = (float*)d_out;

    int n = in_sizes[0] / DD;   // 80000
    int e = in_sizes[1] / 2;    // 1280000
    const int* src = ei;
    const int* dst = ei + e;

    const int T = 256;
    int g_n    = (n + T - 1) / T;
    int g_e    = (e + T - 1) / T;
    int g_rows = (n + 63) / 64;
    int g_warp = (n * 32 + T - 1) / T;
    long long e8 = (long long)e * 8;
    int g_e8 = (int)((e8 + T - 1) / T);

    k_init <<<g_n, T>>>(n);
    k_build<<<g_e, T>>>(src, dst, e);
    k_gemm <<<g_rows, T>>>(X, W, n);
    k_agg  <<<g_warp, T>>>(b, n);
    k_gate <<<g_e8, T>>>(src, dst, e);
    k_out  <<<g_n, T>>>(out, n);
}